// round 6
// baseline (speedup 1.0000x reference)
#include <cuda_runtime.h>
#include <math.h>

// Problem constants
#define B_     4096
#define NSLOTS 64
#define DSLOT  1024
#define DWORK  1024
#define DIN    2048   // DSLOT + DWORK
#define H1_    512
#define H2_    256
#define M_     16

// -------------------- scratch (static device globals; no allocs) ------------
__device__ __align__(16) float g_x   [B_ * DIN];   // pooled||work   32 MB
__device__ __align__(16) float g_w1t [DIN * H1_];  // W1^T            4 MB
__device__ __align__(16) float g_w2t [H1_ * H2_];  // W2^T          0.5 MB
__device__ __align__(16) float g_hpre[B_ * H1_];   // pre-LN          8 MB
__device__ __align__(16) float g_h1  [B_ * H1_];   //                 8 MB
__device__ __align__(16) float g_h2  [B_ * H2_];   //                 4 MB

typedef unsigned long long ull;

// -------------------- packed fp32x2 helpers (sm_100+) -----------------------
__device__ __forceinline__ ull dup2(float a) {
    ull r; asm("mov.b64 %0, {%1, %1};" : "=l"(r) : "f"(a)); return r;
}
__device__ __forceinline__ void fma2(ull &c, ull a, ull b) {
    asm("fma.rn.f32x2 %0, %1, %2, %0;" : "+l"(c) : "l"(a), "l"(b));
}
__device__ __forceinline__ void unpack2(ull v, float &lo, float &hi) {
    asm("mov.b64 {%0, %1}, %2;" : "=f"(lo), "=f"(hi) : "l"(v));
}
__device__ __forceinline__ float gelu_exact(float v) {
    return 0.5f * v * (1.0f + erff(v * 0.70710678118654752440f));
}

// -------------------- weight transpose (rowsxcols -> colsxrows) -------------
__global__ void transpose_k(const float* __restrict__ in, float* __restrict__ out,
                            int R, int C) {
    __shared__ float t[32][33];
    int c0 = blockIdx.x * 32, r0 = blockIdx.y * 32;
#pragma unroll
    for (int i = 0; i < 32; i += 8)
        t[threadIdx.y + i][threadIdx.x] = in[(size_t)(r0 + threadIdx.y + i) * C + c0 + threadIdx.x];
    __syncthreads();
#pragma unroll
    for (int i = 0; i < 32; i += 8)
        out[(size_t)(c0 + threadIdx.y + i) * R + r0 + threadIdx.x] = t[threadIdx.x][threadIdx.y + i];
}

// -------------------- mean-pool + concat ------------------------------------
__device__ __forceinline__ void add4(float4 &a, float4 v) {
    a.x += v.x; a.y += v.y; a.z += v.z; a.w += v.w;
}
__global__ void pool_k(const float* __restrict__ slots, const float* __restrict__ wm,
                       float* __restrict__ x) {
    int b = blockIdx.x, tid = threadIdx.x;  // 256 threads
    const float4* s4 = reinterpret_cast<const float4*>(slots) + (size_t)b * (NSLOTS * DSLOT / 4);
    float4 a0 = make_float4(0,0,0,0), a1 = a0, a2 = a0, a3 = a0;
#pragma unroll
    for (int n = 0; n < NSLOTS; n += 4) {
        float4 v0 = s4[(n + 0) * (DSLOT / 4) + tid];
        float4 v1 = s4[(n + 1) * (DSLOT / 4) + tid];
        float4 v2 = s4[(n + 2) * (DSLOT / 4) + tid];
        float4 v3 = s4[(n + 3) * (DSLOT / 4) + tid];
        add4(a0, v0); add4(a1, v1); add4(a2, v2); add4(a3, v3);
    }
    add4(a0, a1); add4(a2, a3); add4(a0, a2);
    const float inv = 1.0f / (float)NSLOTS;
    float4 m = make_float4(a0.x * inv, a0.y * inv, a0.z * inv, a0.w * inv);
    float4* x4 = reinterpret_cast<float4*>(x) + (size_t)b * (DIN / 4);
    x4[tid] = m;
    x4[(DSLOT / 4) + tid] = reinterpret_cast<const float4*>(wm)[(size_t)b * (DWORK / 4) + tid];
}

// -------------------- tiled fp32 GEMM, packed FFMA2 -------------------------
// C[M,N] = A[M,K] @ Bm[K,N] + bias[N]   (EPI=1: GELU epilogue)
template<int BM, int BN, int BK, int TM, int TN, int EPI>
__global__ __launch_bounds__(256, 1)
void gemm_k(const float* __restrict__ A, const float* __restrict__ Bm,
            const float* __restrict__ bias, float* __restrict__ C,
            int M, int N, int K) {
    constexpr int NT  = 256;
    constexpr int TX  = BN / TN;
    constexpr int TYc = BM / TM;
    static_assert(TX * TYc == NT, "thread grid");
    constexpr int AF  = BM * BK / 4 / NT;   // float4 per thread (A tile)
    constexpr int BF  = BK * BN / 4 / NT;   // float4 per thread (B tile)
    constexpr int LDA = BM + 1;             // padded to avoid STS conflicts

    __shared__ __align__(16) float As[BK * LDA];
    __shared__ __align__(16) float Bs[BK * BN];

    const int tid = threadIdx.x;
    const int tx = tid % TX, ty = tid / TX;
    const int rowBase = blockIdx.y * BM;
    const int colBase = blockIdx.x * BN;

    float4 ar[AF], br[BF];
    ull acc[TM][TN / 2];
#pragma unroll
    for (int i = 0; i < TM; i++)
#pragma unroll
        for (int j = 0; j < TN / 2; j++) acc[i][j] = 0ull;

    const int KT = K / BK;

    auto ldg = [&](int kt) {
#pragma unroll
        for (int i = 0; i < AF; i++) {
            int f = tid + i * NT;
            int r = f / (BK / 4), q = f % (BK / 4);
            ar[i] = *reinterpret_cast<const float4*>(
                &A[(size_t)(rowBase + r) * K + kt * BK + q * 4]);
        }
#pragma unroll
        for (int i = 0; i < BF; i++) {
            int f = tid + i * NT;
            int r = f / (BN / 4), q = f % (BN / 4);
            br[i] = *reinterpret_cast<const float4*>(
                &Bm[(size_t)(kt * BK + r) * N + colBase + q * 4]);
        }
    };
    auto sts = [&]() {
#pragma unroll
        for (int i = 0; i < AF; i++) {
            int f = tid + i * NT;
            int r = f / (BK / 4), q = f % (BK / 4);
            As[(q * 4 + 0) * LDA + r] = ar[i].x;
            As[(q * 4 + 1) * LDA + r] = ar[i].y;
            As[(q * 4 + 2) * LDA + r] = ar[i].z;
            As[(q * 4 + 3) * LDA + r] = ar[i].w;
        }
#pragma unroll
        for (int i = 0; i < BF; i++) {
            int f = tid + i * NT;
            int r = f / (BN / 4), q = f % (BN / 4);
            *reinterpret_cast<float4*>(&Bs[r * BN + q * 4]) = br[i];
        }
    };
    auto comp = [&]() {
#pragma unroll
        for (int k = 0; k < BK; k++) {
            ull pa[TM], pb[TN / 2];
#pragma unroll
            for (int i = 0; i < TM; i++) pa[i] = dup2(As[k * LDA + ty * TM + i]);
#pragma unroll
            for (int j = 0; j < TN / 2; j++)
                pb[j] = *reinterpret_cast<const ull*>(&Bs[k * BN + tx * TN + 2 * j]);
#pragma unroll
            for (int i = 0; i < TM; i++)
#pragma unroll
                for (int j = 0; j < TN / 2; j++) fma2(acc[i][j], pa[i], pb[j]);
        }
    };

    ldg(0); sts(); __syncthreads();
    for (int t = 0; t < KT; t++) {
        if (t + 1 < KT) ldg(t + 1);       // prefetch next tile into regs
        comp();                            // FMA-pipe-bound compute from smem
        __syncthreads();
        if (t + 1 < KT) { sts(); __syncthreads(); }
    }

    // epilogue: bias (+GELU), vectorized stores
#pragma unroll
    for (int i = 0; i < TM; i++) {
        int r = rowBase + ty * TM + i;
        float o[TN];
#pragma unroll
        for (int j = 0; j < TN / 2; j++) unpack2(acc[i][j], o[2 * j], o[2 * j + 1]);
#pragma unroll
        for (int j = 0; j < TN; j++) {
            float v = o[j] + bias[colBase + tx * TN + j];
            if (EPI == 1) v = gelu_exact(v);
            o[j] = v;
        }
#pragma unroll
        for (int q = 0; q < TN / 4; q++)
            *reinterpret_cast<float4*>(&C[(size_t)r * N + colBase + tx * TN + q * 4]) =
                make_float4(o[4 * q], o[4 * q + 1], o[4 * q + 2], o[4 * q + 3]);
    }
}

// -------------------- LayerNorm(512) + GELU ---------------------------------
__global__ void ln_gelu_k(const float* __restrict__ hpre,
                          const float* __restrict__ gamma,
                          const float* __restrict__ beta,
                          float* __restrict__ out) {
    int b = blockIdx.x, tid = threadIdx.x;   // 128 threads, 4 elems each
    const float4* in = reinterpret_cast<const float4*>(hpre + (size_t)b * H1_);
    float4 v = in[tid];
    float s = v.x + v.y + v.z + v.w;
    float q = v.x * v.x + v.y * v.y + v.z * v.z + v.w * v.w;
#pragma unroll
    for (int o = 16; o; o >>= 1) {
        s += __shfl_xor_sync(0xFFFFFFFFu, s, o);
        q += __shfl_xor_sync(0xFFFFFFFFu, q, o);
    }
    __shared__ float rs_[4], rq_[4];
    int w = tid >> 5;
    if ((tid & 31) == 0) { rs_[w] = s; rq_[w] = q; }
    __syncthreads();
    s = rs_[0] + rs_[1] + rs_[2] + rs_[3];
    q = rq_[0] + rq_[1] + rq_[2] + rq_[3];
    float mu   = s * (1.0f / H1_);
    float var  = q * (1.0f / H1_) - mu * mu;
    float rstd = rsqrtf(var + 1e-5f);
    float4 g  = reinterpret_cast<const float4*>(gamma)[tid];
    float4 bt = reinterpret_cast<const float4*>(beta)[tid];
    float4 o;
    o.x = gelu_exact((v.x - mu) * rstd * g.x + bt.x);
    o.y = gelu_exact((v.y - mu) * rstd * g.y + bt.y);
    o.z = gelu_exact((v.z - mu) * rstd * g.z + bt.z);
    o.w = gelu_exact((v.w - mu) * rstd * g.w + bt.w);
    reinterpret_cast<float4*>(out + (size_t)b * H1_)[tid] = o;
}

// -------------------- GEMM3 (K=256, M outputs=16) + gumbel softmax ----------
__global__ void final_k(const float* __restrict__ h2, const float* __restrict__ W3,
                        const float* __restrict__ b3, const float* __restrict__ gn,
                        float* __restrict__ out) {
    int b = blockIdx.x, tid = threadIdx.x;   // 128 threads
    __shared__ float hrow[H2_];
    __shared__ float lg[M_];
    hrow[tid]       = h2[(size_t)b * H2_ + tid];
    hrow[tid + 128] = h2[(size_t)b * H2_ + tid + 128];
    __syncthreads();
    int w = tid >> 5, lane = tid & 31;
#pragma unroll
    for (int mm = 0; mm < 4; mm++) {
        int m = w * 4 + mm;
        const float* wrow = W3 + m * H2_;
        float s = 0.f;
#pragma unroll
        for (int t = lane; t < H2_; t += 32) s += hrow[t] * wrow[t];
#pragma unroll
        for (int o = 16; o; o >>= 1) s += __shfl_xor_sync(0xFFFFFFFFu, s, o);
        if (lane == 0) lg[m] = s + b3[m] + gn[(size_t)b * M_ + m];   // TAU = 1
    }
    __syncthreads();
    if (w == 0) {
        float v = (lane < M_) ? lg[lane] : -1e30f;
        float mx = v;
#pragma unroll
        for (int o = 16; o; o >>= 1) mx = fmaxf(mx, __shfl_xor_sync(0xFFFFFFFFu, mx, o));
        float e = (lane < M_) ? expf(v - mx) : 0.f;
        float ss = e;
#pragma unroll
        for (int o = 16; o; o >>= 1) ss += __shfl_xor_sync(0xFFFFFFFFu, ss, o);
        if (lane < M_) out[(size_t)b * M_ + lane] = e / ss;
    }
}

// -------------------- launch ------------------------------------------------
extern "C" void kernel_launch(void* const* d_in, const int* in_sizes, int n_in,
                              void* d_out, int out_size) {
    const float* slots = (const float*)d_in[0];
    const float* wm    = (const float*)d_in[1];
    const float* gn    = (const float*)d_in[2];
    const float* W1    = (const float*)d_in[3];
    const float* b1    = (const float*)d_in[4];
    const float* gamma = (const float*)d_in[5];
    const float* beta  = (const float*)d_in[6];
    const float* W2    = (const float*)d_in[7];
    const float* b2    = (const float*)d_in[8];
    const float* W3    = (const float*)d_in[9];
    const float* b3    = (const float*)d_in[10];
    float* out = (float*)d_out;

    float *x, *w1t, *w2t, *hpre, *h1, *h2;
    cudaGetSymbolAddress((void**)&x,    g_x);
    cudaGetSymbolAddress((void**)&w1t,  g_w1t);
    cudaGetSymbolAddress((void**)&w2t,  g_w2t);
    cudaGetSymbolAddress((void**)&hpre, g_hpre);
    cudaGetSymbolAddress((void**)&h1,   g_h1);
    cudaGetSymbolAddress((void**)&h2,   g_h2);

    // weight transposes (tiny)
    transpose_k<<<dim3(DIN / 32, H1_ / 32), dim3(32, 8)>>>(W1, w1t, H1_, DIN);
    transpose_k<<<dim3(H1_ / 32, H2_ / 32), dim3(32, 8)>>>(W2, w2t, H2_, H1_);

    // mean-pool + concat (HBM-bound, ~1.07 GB)
    pool_k<<<B_, 256>>>(slots, wm, x);

    // GEMM1: [4096,2048] @ [2048,512] -> hpre  (128 CTAs of 128x128)
    gemm_k<128, 128, 16, 8, 8, 0><<<dim3(H1_ / 128, B_ / 128), 256>>>(
        x, w1t, b1, hpre, B_, H1_, DIN);

    // LayerNorm + GELU
    ln_gelu_k<<<B_, 128>>>(hpre, gamma, beta, h1);

    // GEMM2: [4096,512] @ [512,256] + GELU  (128 CTAs of 64x128)
    gemm_k<64, 128, 16, 4, 8, 1><<<dim3(H2_ / 128, B_ / 64), 256>>>(
        h1, w2t, b2, h2, B_, H2_, H1_);

    // GEMM3 + gumbel softmax
    final_k<<<B_, 128>>>(h2, W3, b3, gn, out);
}

// round 7
// speedup vs baseline: 1.0202x; 1.0202x over previous
#include <cuda_runtime.h>
#include <math.h>

// Problem constants
#define B_     4096
#define NSLOTS 64
#define DSLOT  1024
#define DWORK  1024
#define DIN    2048   // DSLOT + DWORK
#define H1_    512
#define H2_    256
#define M_     16

// -------------------- scratch (static device globals; no allocs) ------------
__device__ __align__(16) float g_x   [B_ * DIN];   // pooled||work   32 MB
__device__ __align__(16) float g_w1t [DIN * H1_];  // W1^T            4 MB
__device__ __align__(16) float g_w2t [H1_ * H2_];  // W2^T          0.5 MB
__device__ __align__(16) float g_hpre[B_ * H1_];   // pre-LN          8 MB
__device__ __align__(16) float g_h1  [B_ * H1_];   //                 8 MB
__device__ __align__(16) float g_h2  [B_ * H2_];   //                 4 MB

typedef unsigned long long ull;

// -------------------- packed fp32x2 helpers (sm_100+) -----------------------
__device__ __forceinline__ ull dup2(float a) {
    ull r; asm("mov.b64 %0, {%1, %1};" : "=l"(r) : "f"(a)); return r;
}
__device__ __forceinline__ void fma2(ull &c, ull a, ull b) {
    asm("fma.rn.f32x2 %0, %1, %2, %0;" : "+l"(c) : "l"(a), "l"(b));
}
__device__ __forceinline__ void unpack2(ull v, float &lo, float &hi) {
    asm("mov.b64 {%0, %1}, %2;" : "=f"(lo), "=f"(hi) : "l"(v));
}
__device__ __forceinline__ float gelu_exact(float v) {
    return 0.5f * v * (1.0f + erff(v * 0.70710678118654752440f));
}

// -------------------- weight transpose (rowsxcols -> colsxrows) -------------
__global__ void transpose_k(const float* __restrict__ in, float* __restrict__ out,
                            int R, int C) {
    __shared__ float t[32][33];
    int c0 = blockIdx.x * 32, r0 = blockIdx.y * 32;
#pragma unroll
    for (int i = 0; i < 32; i += 8)
        t[threadIdx.y + i][threadIdx.x] = in[(size_t)(r0 + threadIdx.y + i) * C + c0 + threadIdx.x];
    __syncthreads();
#pragma unroll
    for (int i = 0; i < 32; i += 8)
        out[(size_t)(c0 + threadIdx.y + i) * R + r0 + threadIdx.x] = t[threadIdx.x][threadIdx.y + i];
}

// -------------------- mean-pool + concat ------------------------------------
__device__ __forceinline__ void add4(float4 &a, float4 v) {
    a.x += v.x; a.y += v.y; a.z += v.z; a.w += v.w;
}
__global__ void pool_k(const float* __restrict__ slots, const float* __restrict__ wm,
                       float* __restrict__ x) {
    int b = blockIdx.x, tid = threadIdx.x;  // 256 threads
    const float4* s4 = reinterpret_cast<const float4*>(slots) + (size_t)b * (NSLOTS * DSLOT / 4);
    float4 a0 = make_float4(0,0,0,0), a1 = a0, a2 = a0, a3 = a0;
#pragma unroll
    for (int n = 0; n < NSLOTS; n += 4) {
        float4 v0 = s4[(n + 0) * (DSLOT / 4) + tid];
        float4 v1 = s4[(n + 1) * (DSLOT / 4) + tid];
        float4 v2 = s4[(n + 2) * (DSLOT / 4) + tid];
        float4 v3 = s4[(n + 3) * (DSLOT / 4) + tid];
        add4(a0, v0); add4(a1, v1); add4(a2, v2); add4(a3, v3);
    }
    add4(a0, a1); add4(a2, a3); add4(a0, a2);
    const float inv = 1.0f / (float)NSLOTS;
    float4 m = make_float4(a0.x * inv, a0.y * inv, a0.z * inv, a0.w * inv);
    float4* x4 = reinterpret_cast<float4*>(x) + (size_t)b * (DIN / 4);
    x4[tid] = m;
    x4[(DSLOT / 4) + tid] = reinterpret_cast<const float4*>(wm)[(size_t)b * (DWORK / 4) + tid];
}

// -------------------- tiled fp32 GEMM, packed FFMA2, double-buffered --------
// C[M,N] = A[M,K] @ Bm[K,N] + bias[N]   (EPI=1: GELU epilogue)
// 128 threads/CTA, 3 CTAs/SM target -> 12 warps/SM -> 3 warps/SMSP.
template<int BM, int BN, int BK, int TM, int TN, int EPI>
__global__ __launch_bounds__(128, 3)
void gemm_k(const float* __restrict__ A, const float* __restrict__ Bm,
            const float* __restrict__ bias, float* __restrict__ C,
            int M, int N, int K) {
    constexpr int NT  = 128;
    constexpr int TX  = BN / TN;
    constexpr int TYc = BM / TM;
    static_assert(TX * TYc == NT, "thread grid");
    constexpr int AF  = BM * BK / 4 / NT;   // float4 per thread (A tile)
    constexpr int BF  = BK * BN / 4 / NT;   // float4 per thread (B tile)
    constexpr int LDA = BM + 1;             // padded to avoid STS conflicts

    __shared__ __align__(16) float As[2][BK * LDA];
    __shared__ __align__(16) float Bs[2][BK * BN];

    const int tid = threadIdx.x;
    const int tx = tid % TX, ty = tid / TX;
    const int rowBase = blockIdx.y * BM;
    const int colBase = blockIdx.x * BN;

    float4 ar[AF], br[BF];
    ull acc[TM][TN / 2];
#pragma unroll
    for (int i = 0; i < TM; i++)
#pragma unroll
        for (int j = 0; j < TN / 2; j++) acc[i][j] = 0ull;

    const int KT = K / BK;

    auto ldg = [&](int kt) {
#pragma unroll
        for (int i = 0; i < AF; i++) {
            int f = tid + i * NT;
            int r = f / (BK / 4), q = f % (BK / 4);
            ar[i] = *reinterpret_cast<const float4*>(
                &A[(size_t)(rowBase + r) * K + kt * BK + q * 4]);
        }
#pragma unroll
        for (int i = 0; i < BF; i++) {
            int f = tid + i * NT;
            int r = f / (BN / 4), q = f % (BN / 4);
            br[i] = *reinterpret_cast<const float4*>(
                &Bm[(size_t)(kt * BK + r) * N + colBase + q * 4]);
        }
    };
    auto sts = [&](int buf) {
#pragma unroll
        for (int i = 0; i < AF; i++) {
            int f = tid + i * NT;
            int r = f / (BK / 4), q = f % (BK / 4);
            As[buf][(q * 4 + 0) * LDA + r] = ar[i].x;
            As[buf][(q * 4 + 1) * LDA + r] = ar[i].y;
            As[buf][(q * 4 + 2) * LDA + r] = ar[i].z;
            As[buf][(q * 4 + 3) * LDA + r] = ar[i].w;
        }
#pragma unroll
        for (int i = 0; i < BF; i++) {
            int f = tid + i * NT;
            int r = f / (BN / 4), q = f % (BN / 4);
            *reinterpret_cast<float4*>(&Bs[buf][r * BN + q * 4]) = br[i];
        }
    };
    auto comp = [&](int buf) {
#pragma unroll
        for (int k = 0; k < BK; k++) {
            ull pa[TM], pb[TN / 2];
#pragma unroll
            for (int i = 0; i < TM; i++) pa[i] = dup2(As[buf][k * LDA + ty * TM + i]);
#pragma unroll
            for (int j = 0; j < TN / 2; j++)
                pb[j] = *reinterpret_cast<const ull*>(&Bs[buf][k * BN + tx * TN + 2 * j]);
#pragma unroll
            for (int i = 0; i < TM; i++)
#pragma unroll
                for (int j = 0; j < TN / 2; j++) fma2(acc[i][j], pa[i], pb[j]);
        }
    };

    // double-buffered mainloop: one __syncthreads per K-tile
    ldg(0); sts(0); __syncthreads();
    for (int t = 0; t < KT; t++) {
        if (t + 1 < KT) ldg(t + 1);        // prefetch next tile (GMEM -> regs)
        comp(t & 1);                        // compute current buffer
        if (t + 1 < KT) sts((t + 1) & 1);   // write other buffer (no readers)
        __syncthreads();
    }

    // epilogue: bias (+GELU), vectorized stores
#pragma unroll
    for (int i = 0; i < TM; i++) {
        int r = rowBase + ty * TM + i;
        float o[TN];
#pragma unroll
        for (int j = 0; j < TN / 2; j++) unpack2(acc[i][j], o[2 * j], o[2 * j + 1]);
#pragma unroll
        for (int j = 0; j < TN; j++) {
            float v = o[j] + bias[colBase + tx * TN + j];
            if (EPI == 1) v = gelu_exact(v);
            o[j] = v;
        }
#pragma unroll
        for (int q = 0; q < TN / 4; q++)
            *reinterpret_cast<float4*>(&C[(size_t)r * N + colBase + tx * TN + q * 4]) =
                make_float4(o[4 * q], o[4 * q + 1], o[4 * q + 2], o[4 * q + 3]);
    }
}

// -------------------- LayerNorm(512) + GELU ---------------------------------
__global__ void ln_gelu_k(const float* __restrict__ hpre,
                          const float* __restrict__ gamma,
                          const float* __restrict__ beta,
                          float* __restrict__ out) {
    int b = blockIdx.x, tid = threadIdx.x;   // 128 threads, 4 elems each
    const float4* in = reinterpret_cast<const float4*>(hpre + (size_t)b * H1_);
    float4 v = in[tid];
    float s = v.x + v.y + v.z + v.w;
    float q = v.x * v.x + v.y * v.y + v.z * v.z + v.w * v.w;
#pragma unroll
    for (int o = 16; o; o >>= 1) {
        s += __shfl_xor_sync(0xFFFFFFFFu, s, o);
        q += __shfl_xor_sync(0xFFFFFFFFu, q, o);
    }
    __shared__ float rs_[4], rq_[4];
    int w = tid >> 5;
    if ((tid & 31) == 0) { rs_[w] = s; rq_[w] = q; }
    __syncthreads();
    s = rs_[0] + rs_[1] + rs_[2] + rs_[3];
    q = rq_[0] + rq_[1] + rq_[2] + rq_[3];
    float mu   = s * (1.0f / H1_);
    float var  = q * (1.0f / H1_) - mu * mu;
    float rstd = rsqrtf(var + 1e-5f);
    float4 g  = reinterpret_cast<const float4*>(gamma)[tid];
    float4 bt = reinterpret_cast<const float4*>(beta)[tid];
    float4 o;
    o.x = gelu_exact((v.x - mu) * rstd * g.x + bt.x);
    o.y = gelu_exact((v.y - mu) * rstd * g.y + bt.y);
    o.z = gelu_exact((v.z - mu) * rstd * g.z + bt.z);
    o.w = gelu_exact((v.w - mu) * rstd * g.w + bt.w);
    reinterpret_cast<float4*>(out + (size_t)b * H1_)[tid] = o;
}

// -------------------- GEMM3 (K=256, M outputs=16) + gumbel softmax ----------
__global__ void final_k(const float* __restrict__ h2, const float* __restrict__ W3,
                        const float* __restrict__ b3, const float* __restrict__ gn,
                        float* __restrict__ out) {
    int b = blockIdx.x, tid = threadIdx.x;   // 128 threads
    __shared__ float hrow[H2_];
    __shared__ float lg[M_];
    hrow[tid]       = h2[(size_t)b * H2_ + tid];
    hrow[tid + 128] = h2[(size_t)b * H2_ + tid + 128];
    __syncthreads();
    int w = tid >> 5, lane = tid & 31;
#pragma unroll
    for (int mm = 0; mm < 4; mm++) {
        int m = w * 4 + mm;
        const float* wrow = W3 + m * H2_;
        float s = 0.f;
#pragma unroll
        for (int t = lane; t < H2_; t += 32) s += hrow[t] * wrow[t];
#pragma unroll
        for (int o = 16; o; o >>= 1) s += __shfl_xor_sync(0xFFFFFFFFu, s, o);
        if (lane == 0) lg[m] = s + b3[m] + gn[(size_t)b * M_ + m];   // TAU = 1
    }
    __syncthreads();
    if (w == 0) {
        float v = (lane < M_) ? lg[lane] : -1e30f;
        float mx = v;
#pragma unroll
        for (int o = 16; o; o >>= 1) mx = fmaxf(mx, __shfl_xor_sync(0xFFFFFFFFu, mx, o));
        float e = (lane < M_) ? expf(v - mx) : 0.f;
        float ss = e;
#pragma unroll
        for (int o = 16; o; o >>= 1) ss += __shfl_xor_sync(0xFFFFFFFFu, ss, o);
        if (lane < M_) out[(size_t)b * M_ + lane] = e / ss;
    }
}

// -------------------- launch ------------------------------------------------
extern "C" void kernel_launch(void* const* d_in, const int* in_sizes, int n_in,
                              void* d_out, int out_size) {
    const float* slots = (const float*)d_in[0];
    const float* wm    = (const float*)d_in[1];
    const float* gn    = (const float*)d_in[2];
    const float* W1    = (const float*)d_in[3];
    const float* b1    = (const float*)d_in[4];
    const float* gamma = (const float*)d_in[5];
    const float* beta  = (const float*)d_in[6];
    const float* W2    = (const float*)d_in[7];
    const float* b2    = (const float*)d_in[8];
    const float* W3    = (const float*)d_in[9];
    const float* b3    = (const float*)d_in[10];
    float* out = (float*)d_out;

    float *x, *w1t, *w2t, *hpre, *h1, *h2;
    cudaGetSymbolAddress((void**)&x,    g_x);
    cudaGetSymbolAddress((void**)&w1t,  g_w1t);
    cudaGetSymbolAddress((void**)&w2t,  g_w2t);
    cudaGetSymbolAddress((void**)&hpre, g_hpre);
    cudaGetSymbolAddress((void**)&h1,   g_h1);
    cudaGetSymbolAddress((void**)&h2,   g_h2);

    // weight transposes (tiny)
    transpose_k<<<dim3(DIN / 32, H1_ / 32), dim3(32, 8)>>>(W1, w1t, H1_, DIN);
    transpose_k<<<dim3(H1_ / 32, H2_ / 32), dim3(32, 8)>>>(W2, w2t, H2_, H1_);

    // mean-pool + concat (HBM-bound, ~1.07 GB)
    pool_k<<<B_, 256>>>(slots, wm, x);

    // GEMM1: [4096,2048] @ [2048,512] -> hpre
    // 128x64 tiles -> 256 CTAs (>=148 SMs), 128 thr, 3 CTAs/SM
    gemm_k<128, 64, 16, 8, 8, 0><<<dim3(H1_ / 64, B_ / 128), 128>>>(
        x, w1t, b1, hpre, B_, H1_, DIN);

    // LayerNorm + GELU
    ln_gelu_k<<<B_, 128>>>(hpre, gamma, beta, h1);

    // GEMM2: [4096,512] @ [512,256] + GELU, 64x64 tiles -> 256 CTAs
    gemm_k<64, 64, 16, 4, 8, 1><<<dim3(H2_ / 64, B_ / 64), 128>>>(
        h1, w2t, b2, h2, B_, H2_, H1_);

    // GEMM3 + gumbel softmax
    final_k<<<B_, 128>>>(h2, W3, b3, gn, out);
}

// round 9
// speedup vs baseline: 1.0251x; 1.0048x over previous
#include <cuda_runtime.h>
#include <math.h>

// Problem constants
#define B_     4096
#define NSLOTS 64
#define DSLOT  1024
#define DWORK  1024
#define DIN    2048
#define H1_    512
#define H2_    256
#define M_     16

// -------------------- scratch (static device globals; no allocs) ------------
__device__ __align__(16) float g_xpool[B_ * DSLOT];  // pooled slots   16 MB
__device__ __align__(16) float g_w1t  [DIN * H1_];   // W1^T            4 MB
__device__ __align__(16) float g_w2t  [H1_ * H2_];   // W2^T          0.5 MB
__device__ __align__(16) float g_hpre [B_ * H1_];    // pre-LN          8 MB
__device__ __align__(16) float g_h1   [B_ * H1_];    //                 8 MB
__device__ __align__(16) float g_h2   [B_ * H2_];    //                 4 MB

typedef unsigned long long ull;

// -------------------- packed fp32x2 helpers (sm_100+) -----------------------
__device__ __forceinline__ ull dup2(float a) {
    ull r; asm("mov.b64 %0, {%1, %1};" : "=l"(r) : "f"(a)); return r;
}
__device__ __forceinline__ void fma2(ull &c, ull a, ull b) {
    asm("fma.rn.f32x2 %0, %1, %2, %0;" : "+l"(c) : "l"(a), "l"(b));
}
__device__ __forceinline__ void unpack2(ull v, float &lo, float &hi) {
    asm("mov.b64 {%0, %1}, %2;" : "=f"(lo), "=f"(hi) : "l"(v));
}
__device__ __forceinline__ float gelu_exact(float v) {
    return 0.5f * v * (1.0f + erff(v * 0.70710678118654752440f));
}

// -------------------- weight transpose --------------------------------------
__global__ void transpose_k(const float* __restrict__ in, float* __restrict__ out,
                            int R, int C) {
    __shared__ float t[32][33];
    int c0 = blockIdx.x * 32, r0 = blockIdx.y * 32;
#pragma unroll
    for (int i = 0; i < 32; i += 8)
        t[threadIdx.y + i][threadIdx.x] = in[(size_t)(r0 + threadIdx.y + i) * C + c0 + threadIdx.x];
    __syncthreads();
#pragma unroll
    for (int i = 0; i < 32; i += 8)
        out[(size_t)(c0 + threadIdx.y + i) * R + r0 + threadIdx.x] = t[threadIdx.x][threadIdx.y + i];
}

// -------------------- GEMM body: packed FFMA2, dup-A smem, double-buffered --
// C[M,N] = A[M,K] @ Bm[K,N] + (ACCUM ? C : bias)     (EPI=1: GELU epilogue)
// 128 threads. A-tile stored in smem as pre-duplicated {a,a} 64-bit pairs so
// the inner loop is pure LDS.64 + FFMA2 (no per-k packing MOVs).
template<int BM, int BN, int BK, int TM, int TN, int EPI, int ACCUM>
__device__ __forceinline__ void gemm_body(
    const float* __restrict__ A, const float* __restrict__ Bm,
    const float* __restrict__ bias, float* __restrict__ C,
    int N, int K, int bx, int by)
{
    constexpr int NT = 128;
    constexpr int TX = BN / TN;                 // 8
    static_assert((BM / TM) * TX == NT, "thread grid");
    constexpr int AF = BM * BK / 4 / NT;        // float4/thread (A tile)
    constexpr int BF = BK * BN / 4 / NT;        // float4/thread (B tile)

    __shared__ __align__(16) ull   As2[2][BK][BM];   // duplicated pairs
    __shared__ __align__(16) float Bs [2][BK][BN];

    const int tid = threadIdx.x;
    const int tx = tid % TX, ty = tid / TX;
    const int rowBase = by * BM, colBase = bx * BN;

    float4 ar[AF], br[BF];
    ull acc[TM][TN / 2];
#pragma unroll
    for (int i = 0; i < TM; i++)
#pragma unroll
        for (int j = 0; j < TN / 2; j++) acc[i][j] = 0ull;

    const int KT = K / BK;

    auto ldg = [&](int kt) {
#pragma unroll
        for (int i = 0; i < AF; i++) {
            int f = tid + i * NT;
            int r = f / (BK / 4), q = f % (BK / 4);
            ar[i] = *reinterpret_cast<const float4*>(
                &A[(size_t)(rowBase + r) * K + kt * BK + q * 4]);
        }
#pragma unroll
        for (int i = 0; i < BF; i++) {
            int f = tid + i * NT;
            int r = f / (BN / 4), q = f % (BN / 4);
            br[i] = *reinterpret_cast<const float4*>(
                &Bm[(size_t)(kt * BK + r) * N + colBase + q * 4]);
        }
    };
    auto sts = [&](int buf) {
#pragma unroll
        for (int i = 0; i < AF; i++) {
            int f = tid + i * NT;
            int r = f / (BK / 4), q = f % (BK / 4);
            As2[buf][q * 4 + 0][r] = dup2(ar[i].x);
            As2[buf][q * 4 + 1][r] = dup2(ar[i].y);
            As2[buf][q * 4 + 2][r] = dup2(ar[i].z);
            As2[buf][q * 4 + 3][r] = dup2(ar[i].w);
        }
#pragma unroll
        for (int i = 0; i < BF; i++) {
            int f = tid + i * NT;
            int r = f / (BN / 4), q = f % (BN / 4);
            *reinterpret_cast<float4*>(&Bs[buf][r][q * 4]) = br[i];
        }
    };
    auto comp = [&](int buf) {
#pragma unroll
        for (int k = 0; k < BK; k++) {
            ull pa[TM], pb[TN / 2];
#pragma unroll
            for (int i = 0; i < TM; i++) pa[i] = As2[buf][k][ty * TM + i];
#pragma unroll
            for (int j = 0; j < TN / 2; j++)
                pb[j] = *reinterpret_cast<const ull*>(&Bs[buf][k][tx * TN + 2 * j]);
#pragma unroll
            for (int i = 0; i < TM; i++)
#pragma unroll
                for (int j = 0; j < TN / 2; j++) fma2(acc[i][j], pa[i], pb[j]);
        }
    };

    ldg(0); sts(0); __syncthreads();
    for (int t = 0; t < KT; t++) {
        if (t + 1 < KT) ldg(t + 1);
        comp(t & 1);
        if (t + 1 < KT) sts((t + 1) & 1);
        __syncthreads();
    }

    // epilogue
    float bb[TN];
    if (!ACCUM) {
#pragma unroll
        for (int j = 0; j < TN; j++) bb[j] = bias[colBase + tx * TN + j];
    }
#pragma unroll
    for (int i = 0; i < TM; i++) {
        int r = rowBase + ty * TM + i;
        float o[TN];
#pragma unroll
        for (int j = 0; j < TN / 2; j++) unpack2(acc[i][j], o[2 * j], o[2 * j + 1]);
        if (ACCUM) {
#pragma unroll
            for (int q = 0; q < TN / 4; q++) {
                float4 p = *reinterpret_cast<const float4*>(
                    &C[(size_t)r * N + colBase + tx * TN + q * 4]);
                o[4 * q + 0] += p.x; o[4 * q + 1] += p.y;
                o[4 * q + 2] += p.z; o[4 * q + 3] += p.w;
            }
        } else {
#pragma unroll
            for (int j = 0; j < TN; j++) o[j] += bb[j];
        }
        if (EPI == 1) {
#pragma unroll
            for (int j = 0; j < TN; j++) o[j] = gelu_exact(o[j]);
        }
#pragma unroll
        for (int q = 0; q < TN / 4; q++)
            *reinterpret_cast<float4*>(&C[(size_t)r * N + colBase + tx * TN + q * 4]) =
                make_float4(o[4 * q], o[4 * q + 1], o[4 * q + 2], o[4 * q + 3]);
    }
}

// -------------------- fused: wm-half GEMM (blocks 0..255) + pool (rest) -----
#define G1_NTILES (H1_ / 64)            // 8
#define G1_BLOCKS (G1_NTILES * (B_ / 128))  // 256

__global__ __launch_bounds__(128, 3)
void fused_pool_wmgemm_k(const float* __restrict__ slots,
                         const float* __restrict__ wm,
                         const float* __restrict__ w1t_wm,  // rows 1024..2047 of W1^T
                         const float* __restrict__ b1,
                         float* __restrict__ xpool,
                         float* __restrict__ hpre)
{
    int gx = blockIdx.x;
    if (gx < G1_BLOCKS) {
        // wm-half of GEMM1: hpre = wm @ W1b^T + b1   (K = 1024)
        gemm_body<128, 64, 16, 8, 8, 0, 0>(wm, w1t_wm, b1, hpre,
                                           H1_, DWORK, gx % G1_NTILES, gx / G1_NTILES);
    } else {
        // mean-pool one batch row (HBM streaming, overlaps with GEMM above)
        int b = gx - G1_BLOCKS;
        int tid = threadIdx.x;   // 128 threads, 8 floats each
        const float4* s4 = reinterpret_cast<const float4*>(slots)
                           + (size_t)b * (NSLOTS * DSLOT / 4);
        float4 a0 = make_float4(0,0,0,0), a1 = a0, b0 = a0, b1v = a0;
#pragma unroll
        for (int n = 0; n < NSLOTS; n += 2) {
            float4 v0 = s4[(n + 0) * (DSLOT / 4) + tid];
            float4 w0 = s4[(n + 0) * (DSLOT / 4) + 128 + tid];
            float4 v1 = s4[(n + 1) * (DSLOT / 4) + tid];
            float4 w1 = s4[(n + 1) * (DSLOT / 4) + 128 + tid];
            a0.x += v0.x; a0.y += v0.y; a0.z += v0.z; a0.w += v0.w;
            b0.x += w0.x; b0.y += w0.y; b0.z += w0.z; b0.w += w0.w;
            a1.x += v1.x; a1.y += v1.y; a1.z += v1.z; a1.w += v1.w;
            b1v.x += w1.x; b1v.y += w1.y; b1v.z += w1.z; b1v.w += w1.w;
        }
        const float inv = 1.0f / (float)NSLOTS;
        float4 m0 = make_float4((a0.x + a1.x) * inv, (a0.y + a1.y) * inv,
                                (a0.z + a1.z) * inv, (a0.w + a1.w) * inv);
        float4 m1 = make_float4((b0.x + b1v.x) * inv, (b0.y + b1v.y) * inv,
                                (b0.z + b1v.z) * inv, (b0.w + b1v.w) * inv);
        float4* x4 = reinterpret_cast<float4*>(xpool) + (size_t)b * (DSLOT / 4);
        x4[tid] = m0;
        x4[128 + tid] = m1;
    }
}

// -------------------- slots-half GEMM (accumulate into hpre) ----------------
__global__ __launch_bounds__(128, 3)
void gemm_slots_k(const float* __restrict__ xpool, const float* __restrict__ w1t,
                  float* __restrict__ hpre)
{
    gemm_body<128, 64, 16, 8, 8, 0, 1>(xpool, w1t, nullptr, hpre,
                                       H1_, DSLOT,
                                       blockIdx.x % G1_NTILES, blockIdx.x / G1_NTILES);
}

// -------------------- GEMM2 + GELU ------------------------------------------
__global__ __launch_bounds__(128, 3)
void gemm2_k(const float* __restrict__ h1, const float* __restrict__ w2t,
             const float* __restrict__ b2, float* __restrict__ h2)
{
    gemm_body<64, 64, 16, 4, 8, 1, 0>(h1, w2t, b2, h2,
                                      H2_, H1_,
                                      blockIdx.x % (H2_ / 64), blockIdx.x / (H2_ / 64));
}

// -------------------- LayerNorm(512) + GELU ---------------------------------
__global__ void ln_gelu_k(const float* __restrict__ hpre,
                          const float* __restrict__ gamma,
                          const float* __restrict__ beta,
                          float* __restrict__ out) {
    int b = blockIdx.x, tid = threadIdx.x;   // 128 threads, 4 elems each
    const float4* in = reinterpret_cast<const float4*>(hpre + (size_t)b * H1_);
    float4 v = in[tid];
    float s = v.x + v.y + v.z + v.w;
    float q = v.x * v.x + v.y * v.y + v.z * v.z + v.w * v.w;
#pragma unroll
    for (int o = 16; o; o >>= 1) {
        s += __shfl_xor_sync(0xFFFFFFFFu, s, o);
        q += __shfl_xor_sync(0xFFFFFFFFu, q, o);
    }
    __shared__ float rs_[4], rq_[4];
    int w = tid >> 5;
    if ((tid & 31) == 0) { rs_[w] = s; rq_[w] = q; }
    __syncthreads();
    s = rs_[0] + rs_[1] + rs_[2] + rs_[3];
    q = rq_[0] + rq_[1] + rq_[2] + rq_[3];
    float mu   = s * (1.0f / H1_);
    float var  = q * (1.0f / H1_) - mu * mu;
    float rstd = rsqrtf(var + 1e-5f);
    float4 g  = reinterpret_cast<const float4*>(gamma)[tid];
    float4 bt = reinterpret_cast<const float4*>(beta)[tid];
    float4 o;
    o.x = gelu_exact((v.x - mu) * rstd * g.x + bt.x);
    o.y = gelu_exact((v.y - mu) * rstd * g.y + bt.y);
    o.z = gelu_exact((v.z - mu) * rstd * g.z + bt.z);
    o.w = gelu_exact((v.w - mu) * rstd * g.w + bt.w);
    reinterpret_cast<float4*>(out + (size_t)b * H1_)[tid] = o;
}

// -------------------- GEMM3 + gumbel softmax --------------------------------
__global__ void final_k(const float* __restrict__ h2, const float* __restrict__ W3,
                        const float* __restrict__ b3, const float* __restrict__ gn,
                        float* __restrict__ out) {
    int b = blockIdx.x, tid = threadIdx.x;   // 128 threads
    __shared__ float hrow[H2_];
    __shared__ float lg[M_];
    hrow[tid]       = h2[(size_t)b * H2_ + tid];
    hrow[tid + 128] = h2[(size_t)b * H2_ + tid + 128];
    __syncthreads();
    int w = tid >> 5, lane = tid & 31;
#pragma unroll
    for (int mm = 0; mm < 4; mm++) {
        int m = w * 4 + mm;
        const float* wrow = W3 + m * H2_;
        float s = 0.f;
#pragma unroll
        for (int t = lane; t < H2_; t += 32) s += hrow[t] * wrow[t];
#pragma unroll
        for (int o = 16; o; o >>= 1) s += __shfl_xor_sync(0xFFFFFFFFu, s, o);
        if (lane == 0) lg[m] = s + b3[m] + gn[(size_t)b * M_ + m];   // TAU = 1
    }
    __syncthreads();
    if (w == 0) {
        float v = (lane < M_) ? lg[lane] : -1e30f;
        float mx = v;
#pragma unroll
        for (int o = 16; o; o >>= 1) mx = fmaxf(mx, __shfl_xor_sync(0xFFFFFFFFu, mx, o));
        float e = (lane < M_) ? expf(v - mx) : 0.f;
        float ss = e;
#pragma unroll
        for (int o = 16; o; o >>= 1) ss += __shfl_xor_sync(0xFFFFFFFFu, ss, o);
        if (lane < M_) out[(size_t)b * M_ + lane] = e / ss;
    }
}

// -------------------- launch ------------------------------------------------
extern "C" void kernel_launch(void* const* d_in, const int* in_sizes, int n_in,
                              void* d_out, int out_size) {
    const float* slots = (const float*)d_in[0];
    const float* wm    = (const float*)d_in[1];
    const float* gn    = (const float*)d_in[2];
    const float* W1    = (const float*)d_in[3];
    const float* b1    = (const float*)d_in[4];
    const float* gamma = (const float*)d_in[5];
    const float* beta  = (const float*)d_in[6];
    const float* W2    = (const float*)d_in[7];
    const float* b2    = (const float*)d_in[8];
    const float* W3    = (const float*)d_in[9];
    const float* b3    = (const float*)d_in[10];
    float* out = (float*)d_out;

    float *xpool, *w1t, *w2t, *hpre, *h1, *h2;
    cudaGetSymbolAddress((void**)&xpool, g_xpool);
    cudaGetSymbolAddress((void**)&w1t,   g_w1t);
    cudaGetSymbolAddress((void**)&w2t,   g_w2t);
    cudaGetSymbolAddress((void**)&hpre,  g_hpre);
    cudaGetSymbolAddress((void**)&h1,    g_h1);
    cudaGetSymbolAddress((void**)&h2,    g_h2);

    // weight transposes (tiny)
    transpose_k<<<dim3(DIN / 32, H1_ / 32), dim3(32, 8)>>>(W1, w1t, H1_, DIN);
    transpose_k<<<dim3(H1_ / 32, H2_ / 32), dim3(32, 8)>>>(W2, w2t, H2_, H1_);

    // fused: wm-half GEMM1 (blocks 0..255, FMA-bound) + mean-pool (HBM-bound)
    fused_pool_wmgemm_k<<<G1_BLOCKS + B_, 128>>>(
        slots, wm, w1t + (size_t)DSLOT * H1_, b1, xpool, hpre);

    // slots-half GEMM1, accumulates into hpre
    gemm_slots_k<<<G1_BLOCKS, 128>>>(xpool, w1t, hpre);

    // LayerNorm + GELU
    ln_gelu_k<<<B_, 128>>>(hpre, gamma, beta, h1);

    // GEMM2 + GELU
    gemm2_k<<<(H2_ / 64) * (B_ / 64), 128>>>(h1, w2t, b2, h2);

    // GEMM3 + gumbel softmax
    final_k<<<B_, 128>>>(h2, W3, b3, gn, out);
}

// round 12
// speedup vs baseline: 1.6254x; 1.5856x over previous
#include <cuda_runtime.h>
#include <cuda_bf16.h>
#include <stdint.h>
#include <math.h>

// Problem constants
#define B_     4096
#define NSLOTS 64
#define DSLOT  1024
#define DWORK  1024
#define DIN    2048
#define H1_    512
#define H2_    256
#define M_     16

// -------------------- scratch (static device globals; no allocs) ------------
__device__ __align__(16) __nv_bfloat16 g_w1h[H1_ * DIN],  g_w1l[H1_ * DIN];
__device__ __align__(16) __nv_bfloat16 g_w2h[H2_ * H1_],  g_w2l[H2_ * H1_];
__device__ __align__(16) __nv_bfloat16 g_wmh[B_ * DWORK], g_wml[B_ * DWORK];
__device__ __align__(16) __nv_bfloat16 g_xph[B_ * DSLOT], g_xpl[B_ * DSLOT];
__device__ __align__(16) __nv_bfloat16 g_h1h[B_ * H1_],   g_h1l[B_ * H1_];
__device__ __align__(16) float g_hpre[B_ * H1_];
__device__ __align__(16) float g_h2  [B_ * H2_];

// -------------------- helpers ------------------------------------------------
__device__ __forceinline__ uint32_t smem_u32(const void* p) {
    uint32_t a;
    asm("{ .reg .u64 t; cvta.to.shared.u64 t, %1; cvt.u32.u64 %0, t; }" : "=r"(a) : "l"(p));
    return a;
}
__device__ __forceinline__ float gelu_exact(float v) {
    return 0.5f * v * (1.0f + erff(v * 0.70710678118654752440f));
}
#define SW128(o) ((o) ^ (((o) >> 3) & 0x70))

#define CP16(dst, src) asm volatile("cp.async.cg.shared.global [%0], [%1], 16;" :: "r"(dst), "l"(src) : "memory")
#define CP_COMMIT()    asm volatile("cp.async.commit_group;" ::: "memory")
#define CP_WAIT0()     asm volatile("cp.async.wait_group 0;" ::: "memory")

__device__ __forceinline__ void ldsm4(uint32_t& r0, uint32_t& r1, uint32_t& r2, uint32_t& r3, uint32_t a) {
    asm volatile("ldmatrix.sync.aligned.m8n8.x4.shared.b16 {%0,%1,%2,%3}, [%4];"
                 : "=r"(r0), "=r"(r1), "=r"(r2), "=r"(r3) : "r"(a));
}
__device__ __forceinline__ void mma16816(float* c, const uint32_t* a, const uint32_t* b) {
    asm volatile("mma.sync.aligned.m16n8k16.row.col.f32.bf16.bf16.f32 "
                 "{%0,%1,%2,%3}, {%4,%5,%6,%7}, {%8,%9}, {%0,%1,%2,%3};"
                 : "+f"(c[0]), "+f"(c[1]), "+f"(c[2]), "+f"(c[3])
                 : "r"(a[0]), "r"(a[1]), "r"(a[2]), "r"(a[3]), "r"(b[0]), "r"(b[1]));
}

// -------------------- split-bf16 mma.sync GEMM -------------------------------
// C[128x64 tile] = (Ah+Al)[M,K] @ (Bh+Bl)[N,K]^T  (3 products, fp32 reg accum)
// A,B are K-major bf16 (hi/lo).  EPI=1: GELU.  ACCUM=1: C += res (no bias).
template<int EPI, int ACCUM>
__device__ __forceinline__ void mma_gemm(
    const __nv_bfloat16* __restrict__ Ah, const __nv_bfloat16* __restrict__ Al, int lda,
    const __nv_bfloat16* __restrict__ Bh, const __nv_bfloat16* __restrict__ Bl, int ldb,
    int K, const float* __restrict__ bias, float* __restrict__ C, int Nc,
    int bx, int by)
{
    __shared__ __align__(1024) __nv_bfloat16 sA[2][128 * 64];  // 32 KB (hi/lo)
    __shared__ __align__(1024) __nv_bfloat16 sB[2][64 * 64];   // 16 KB

    const int tid = threadIdx.x, wid = tid >> 5, lane = tid & 31;
    const uint32_t aB0 = smem_u32(sA[0]), aB1 = smem_u32(sA[1]);
    const uint32_t bB0 = smem_u32(sB[0]), bB1 = smem_u32(sB[1]);

    float acc[2][8][4];
#pragma unroll
    for (int i = 0; i < 2; i++)
#pragma unroll
        for (int j = 0; j < 8; j++)
#pragma unroll
            for (int q = 0; q < 4; q++) acc[i][j][q] = 0.f;

    const int rowA = by * 128, rowB = bx * 64;
    // ldmatrix per-lane row / k-byte offsets (standard m16n8k16 fragment maps)
    const int arow = (lane & 7) + ((lane >> 3) & 1) * 8;   // A: m within tile
    const int akb  = (lane >> 4) * 16;                     // A: k-byte half
    const int brow = (lane & 7) + (lane >> 4) * 8;         // B: n within n16 group
    const int bkb  = ((lane >> 3) & 1) * 16;               // B: k-byte half

    const int KT = K / 64;
    for (int c = 0; c < KT; c++) {
        const int k0 = c * 64;
        // ---- load chunk (A: 128x64, B: 64x64, hi+lo) via cp.async, SW128 ----
        {
            const char* pH = (const char*)(Ah + (size_t)(rowA + tid) * lda + k0);
            const char* pL = (const char*)(Al + (size_t)(rowA + tid) * lda + k0);
#pragma unroll
            for (int i = 0; i < 8; i++) {
                uint32_t o = SW128((uint32_t)(tid * 128 + i * 16));
                CP16(aB0 + o, pH + i * 16);
                CP16(aB1 + o, pL + i * 16);
            }
            const int rb = tid >> 1, hb = (tid & 1) * 64;   // 64 rows, half-rows
            const char* qH = (const char*)(Bh + (size_t)(rowB + rb) * ldb + k0) + hb;
            const char* qL = (const char*)(Bl + (size_t)(rowB + rb) * ldb + k0) + hb;
#pragma unroll
            for (int i = 0; i < 4; i++) {
                uint32_t o = SW128((uint32_t)(rb * 128 + hb + i * 16));
                CP16(bB0 + o, qH + i * 16);
                CP16(bB1 + o, qL + i * 16);
            }
        }
        CP_COMMIT(); CP_WAIT0();
        __syncthreads();

        // ---- compute: 4 k16 steps ----
#pragma unroll
        for (int ks = 0; ks < 4; ks++) {
            const int kb = ks * 32;
            uint32_t afr[2][2][4];   // [hi/lo][m-tile][4]
            uint32_t bfr[2][8][2];   // [hi/lo][n8-tile][2]
#pragma unroll
            for (int mt = 0; mt < 2; mt++) {
                uint32_t o = SW128((uint32_t)((wid * 32 + mt * 16 + arow) * 128 + kb + akb));
                ldsm4(afr[0][mt][0], afr[0][mt][1], afr[0][mt][2], afr[0][mt][3], aB0 + o);
                ldsm4(afr[1][mt][0], afr[1][mt][1], afr[1][mt][2], afr[1][mt][3], aB1 + o);
            }
#pragma unroll
            for (int ng = 0; ng < 4; ng++) {
                uint32_t o = SW128((uint32_t)((ng * 16 + brow) * 128 + kb + bkb));
                ldsm4(bfr[0][2 * ng][0], bfr[0][2 * ng][1],
                      bfr[0][2 * ng + 1][0], bfr[0][2 * ng + 1][1], bB0 + o);
                ldsm4(bfr[1][2 * ng][0], bfr[1][2 * ng][1],
                      bfr[1][2 * ng + 1][0], bfr[1][2 * ng + 1][1], bB1 + o);
            }
#pragma unroll
            for (int mt = 0; mt < 2; mt++)
#pragma unroll
                for (int nt = 0; nt < 8; nt++) {
                    mma16816(acc[mt][nt], afr[0][mt], bfr[0][nt]);   // ah*bh
                    mma16816(acc[mt][nt], afr[0][mt], bfr[1][nt]);   // ah*bl
                    mma16816(acc[mt][nt], afr[1][mt], bfr[0][nt]);   // al*bh
                }
        }
        __syncthreads();
    }

    // ---- epilogue: fragment -> C with bias(+GELU) or accumulate ----
    const int r0 = rowA + wid * 32 + lane / 4;
    const int cB = rowB + (lane % 4) * 2;
#pragma unroll
    for (int mt = 0; mt < 2; mt++)
#pragma unroll
        for (int nt = 0; nt < 8; nt++)
#pragma unroll
            for (int g = 0; g < 2; g++) {
                const int rr = r0 + mt * 16 + g * 8;
                const int cc = cB + nt * 8;
                float2 v = make_float2(acc[mt][nt][2 * g], acc[mt][nt][2 * g + 1]);
                float* p = C + (size_t)rr * Nc + cc;
                if (ACCUM) {
                    float2 pv = *reinterpret_cast<const float2*>(p);
                    v.x += pv.x; v.y += pv.y;
                } else {
                    v.x += bias[cc]; v.y += bias[cc + 1];
                }
                if (EPI) { v.x = gelu_exact(v.x); v.y = gelu_exact(v.y); }
                *reinterpret_cast<float2*>(p) = v;
            }
}

// -------------------- fp32 -> bf16 hi/lo split conversion --------------------
__global__ void convert_split_k(const float* __restrict__ src,
                                __nv_bfloat16* __restrict__ h, __nv_bfloat16* __restrict__ l) {
    int i = blockIdx.x * 256 + threadIdx.x;            // float4 index
    float4 v = reinterpret_cast<const float4*>(src)[i];
    __nv_bfloat16 hh[4], ll[4];
    float f[4] = {v.x, v.y, v.z, v.w};
#pragma unroll
    for (int j = 0; j < 4; j++) {
        hh[j] = __float2bfloat16(f[j]);
        ll[j] = __float2bfloat16(f[j] - __bfloat162float(hh[j]));
    }
    reinterpret_cast<uint2*>(h)[i] = *reinterpret_cast<uint2*>(hh);
    reinterpret_cast<uint2*>(l)[i] = *reinterpret_cast<uint2*>(ll);
}

// -------------------- fused: wm-half GEMM1 (mma) + pool ----------------------
#define G1_BLOCKS 256   // 32 row-tiles x 8 col-tiles (N=512/64)

__global__ void __launch_bounds__(128)
fused_pool_wm_k(const float* __restrict__ slots,
                const float* __restrict__ b1,
                __nv_bfloat16* __restrict__ xph, __nv_bfloat16* __restrict__ xpl,
                float* __restrict__ hpre)
{
    int gx = blockIdx.x;
    if (gx < G1_BLOCKS) {
        // hpre = wm @ W1[:,1024:2048]^T + b1   (K = 1024)
        mma_gemm<0, 0>(g_wmh, g_wml, DWORK,
                       g_w1h + DSLOT, g_w1l + DSLOT, DIN,
                       DWORK, b1, hpre, H1_, gx & 7, gx >> 3);
    } else {
        // mean-pool one batch row -> bf16 hi/lo (HBM streaming, overlaps GEMM)
        int b = gx - G1_BLOCKS;
        int tid = threadIdx.x;   // 128 threads, 8 floats each
        const float4* s4 = reinterpret_cast<const float4*>(slots)
                           + (size_t)b * (NSLOTS * DSLOT / 4);
        float4 a0 = make_float4(0, 0, 0, 0), a1 = a0, c0 = a0, c1 = a0;
#pragma unroll
        for (int n = 0; n < NSLOTS; n += 2) {
            float4 v0 = s4[(n + 0) * (DSLOT / 4) + tid];
            float4 w0 = s4[(n + 0) * (DSLOT / 4) + 128 + tid];
            float4 v1 = s4[(n + 1) * (DSLOT / 4) + tid];
            float4 w1 = s4[(n + 1) * (DSLOT / 4) + 128 + tid];
            a0.x += v0.x; a0.y += v0.y; a0.z += v0.z; a0.w += v0.w;
            c0.x += w0.x; c0.y += w0.y; c0.z += w0.z; c0.w += w0.w;
            a1.x += v1.x; a1.y += v1.y; a1.z += v1.z; a1.w += v1.w;
            c1.x += w1.x; c1.y += w1.y; c1.z += w1.z; c1.w += w1.w;
        }
        const float inv = 1.0f / (float)NSLOTS;
        float m0[4] = {(a0.x + a1.x) * inv, (a0.y + a1.y) * inv, (a0.z + a1.z) * inv, (a0.w + a1.w) * inv};
        float m1[4] = {(c0.x + c1.x) * inv, (c0.y + c1.y) * inv, (c0.z + c1.z) * inv, (c0.w + c1.w) * inv};
        __nv_bfloat16 hh[4], ll[4];
#pragma unroll
        for (int j = 0; j < 4; j++) {
            hh[j] = __float2bfloat16(m0[j]);
            ll[j] = __float2bfloat16(m0[j] - __bfloat162float(hh[j]));
        }
        size_t base = (size_t)b * DSLOT + tid * 4;
        *reinterpret_cast<uint2*>(&xph[base]) = *reinterpret_cast<uint2*>(hh);
        *reinterpret_cast<uint2*>(&xpl[base]) = *reinterpret_cast<uint2*>(ll);
#pragma unroll
        for (int j = 0; j < 4; j++) {
            hh[j] = __float2bfloat16(m1[j]);
            ll[j] = __float2bfloat16(m1[j] - __bfloat162float(hh[j]));
        }
        *reinterpret_cast<uint2*>(&xph[base + 512]) = *reinterpret_cast<uint2*>(hh);
        *reinterpret_cast<uint2*>(&xpl[base + 512]) = *reinterpret_cast<uint2*>(ll);
    }
}

// -------------------- slots-half GEMM1 (accumulate into hpre) ----------------
__global__ void __launch_bounds__(128)
gemm_slots_mma_k(float* __restrict__ hpre)
{
    mma_gemm<0, 1>(g_xph, g_xpl, DSLOT, g_w1h, g_w1l, DIN,
                   DSLOT, nullptr, hpre, H1_, blockIdx.x & 7, blockIdx.x >> 3);
}

// -------------------- GEMM2 (+bias+GELU) -------------------------------------
__global__ void __launch_bounds__(128)
gemm2_mma_k(const float* __restrict__ b2, float* __restrict__ h2)
{
    mma_gemm<1, 0>(g_h1h, g_h1l, H1_, g_w2h, g_w2l, H1_,
                   H1_, b2, h2, H2_, blockIdx.x & 3, blockIdx.x >> 2);
}

// -------------------- LayerNorm(512) + GELU -> bf16 hi/lo --------------------
__global__ void ln_gelu_k(const float* __restrict__ hpre,
                          const float* __restrict__ gamma,
                          const float* __restrict__ beta,
                          __nv_bfloat16* __restrict__ h1h,
                          __nv_bfloat16* __restrict__ h1l) {
    int b = blockIdx.x, tid = threadIdx.x;   // 128 threads, 4 elems each
    const float4* in = reinterpret_cast<const float4*>(hpre + (size_t)b * H1_);
    float4 v = in[tid];
    float s = v.x + v.y + v.z + v.w;
    float q = v.x * v.x + v.y * v.y + v.z * v.z + v.w * v.w;
#pragma unroll
    for (int o = 16; o; o >>= 1) {
        s += __shfl_xor_sync(0xFFFFFFFFu, s, o);
        q += __shfl_xor_sync(0xFFFFFFFFu, q, o);
    }
    __shared__ float rs_[4], rq_[4];
    int w = tid >> 5;
    if ((tid & 31) == 0) { rs_[w] = s; rq_[w] = q; }
    __syncthreads();
    s = rs_[0] + rs_[1] + rs_[2] + rs_[3];
    q = rq_[0] + rq_[1] + rq_[2] + rq_[3];
    float mu   = s * (1.0f / H1_);
    float var  = q * (1.0f / H1_) - mu * mu;
    float rstd = rsqrtf(var + 1e-5f);
    float4 g  = reinterpret_cast<const float4*>(gamma)[tid];
    float4 bt = reinterpret_cast<const float4*>(beta)[tid];
    float o[4];
    o[0] = gelu_exact((v.x - mu) * rstd * g.x + bt.x);
    o[1] = gelu_exact((v.y - mu) * rstd * g.y + bt.y);
    o[2] = gelu_exact((v.z - mu) * rstd * g.z + bt.z);
    o[3] = gelu_exact((v.w - mu) * rstd * g.w + bt.w);
    __nv_bfloat16 hh[4], ll[4];
#pragma unroll
    for (int j = 0; j < 4; j++) {
        hh[j] = __float2bfloat16(o[j]);
        ll[j] = __float2bfloat16(o[j] - __bfloat162float(hh[j]));
    }
    size_t base = (size_t)b * H1_ + tid * 4;
    *reinterpret_cast<uint2*>(&h1h[base]) = *reinterpret_cast<uint2*>(hh);
    *reinterpret_cast<uint2*>(&h1l[base]) = *reinterpret_cast<uint2*>(ll);
}

// -------------------- GEMM3 + gumbel softmax ---------------------------------
__global__ void final_k(const float* __restrict__ h2, const float* __restrict__ W3,
                        const float* __restrict__ b3, const float* __restrict__ gn,
                        float* __restrict__ out) {
    int b = blockIdx.x, tid = threadIdx.x;   // 128 threads
    __shared__ float hrow[H2_];
    __shared__ float lg[M_];
    hrow[tid]       = h2[(size_t)b * H2_ + tid];
    hrow[tid + 128] = h2[(size_t)b * H2_ + tid + 128];
    __syncthreads();
    int w = tid >> 5, lane = tid & 31;
#pragma unroll
    for (int mm = 0; mm < 4; mm++) {
        int m = w * 4 + mm;
        const float* wrow = W3 + m * H2_;
        float s = 0.f;
#pragma unroll
        for (int t = lane; t < H2_; t += 32) s += hrow[t] * wrow[t];
#pragma unroll
        for (int o = 16; o; o >>= 1) s += __shfl_xor_sync(0xFFFFFFFFu, s, o);
        if (lane == 0) lg[m] = s + b3[m] + gn[(size_t)b * M_ + m];   // TAU = 1
    }
    __syncthreads();
    if (w == 0) {
        float v = (lane < M_) ? lg[lane] : -1e30f;
        float mx = v;
#pragma unroll
        for (int o = 16; o; o >>= 1) mx = fmaxf(mx, __shfl_xor_sync(0xFFFFFFFFu, mx, o));
        float e = (lane < M_) ? expf(v - mx) : 0.f;
        float ss = e;
#pragma unroll
        for (int o = 16; o; o >>= 1) ss += __shfl_xor_sync(0xFFFFFFFFu, ss, o);
        if (lane < M_) out[(size_t)b * M_ + lane] = e / ss;
    }
}

// -------------------- launch -------------------------------------------------
extern "C" void kernel_launch(void* const* d_in, const int* in_sizes, int n_in,
                              void* d_out, int out_size) {
    const float* slots = (const float*)d_in[0];
    const float* wm    = (const float*)d_in[1];
    const float* gn    = (const float*)d_in[2];
    const float* W1    = (const float*)d_in[3];
    const float* b1    = (const float*)d_in[4];
    const float* gamma = (const float*)d_in[5];
    const float* beta  = (const float*)d_in[6];
    const float* W2    = (const float*)d_in[7];
    const float* b2    = (const float*)d_in[8];
    const float* W3    = (const float*)d_in[9];
    const float* b3    = (const float*)d_in[10];
    float* out = (float*)d_out;

    __nv_bfloat16 *w1h, *w1l, *w2h, *w2l, *wmh, *wml, *xph, *xpl, *h1h, *h1l;
    float *hpre, *h2;
    cudaGetSymbolAddress((void**)&w1h, g_w1h);  cudaGetSymbolAddress((void**)&w1l, g_w1l);
    cudaGetSymbolAddress((void**)&w2h, g_w2h);  cudaGetSymbolAddress((void**)&w2l, g_w2l);
    cudaGetSymbolAddress((void**)&wmh, g_wmh);  cudaGetSymbolAddress((void**)&wml, g_wml);
    cudaGetSymbolAddress((void**)&xph, g_xph);  cudaGetSymbolAddress((void**)&xpl, g_xpl);
    cudaGetSymbolAddress((void**)&h1h, g_h1h);  cudaGetSymbolAddress((void**)&h1l, g_h1l);
    cudaGetSymbolAddress((void**)&hpre, g_hpre);
    cudaGetSymbolAddress((void**)&h2,   g_h2);

    // bf16 hi/lo conversions (small)
    convert_split_k<<<(H1_ * DIN)  / 1024, 256>>>(W1, w1h, w1l);
    convert_split_k<<<(H2_ * H1_)  / 1024, 256>>>(W2, w2h, w2l);
    convert_split_k<<<(B_ * DWORK) / 1024, 256>>>(wm, wmh, wml);

    // fused: wm-half GEMM1 (mma.sync, blocks 0..255) + mean-pool -> bf16 (rest)
    fused_pool_wm_k<<<G1_BLOCKS + B_, 128>>>(slots, b1, xph, xpl, hpre);

    // slots-half GEMM1 (mma.sync), accumulate into hpre
    gemm_slots_mma_k<<<G1_BLOCKS, 128>>>(hpre);

    // LayerNorm + GELU -> bf16 hi/lo
    ln_gelu_k<<<B_, 128>>>(hpre, gamma, beta, h1h, h1l);

    // GEMM2 (mma.sync) + bias + GELU -> h2 fp32   (32 row-tiles x 4 col-tiles)
    gemm2_mma_k<<<(H2_ / 64) * (B_ / 128), 128>>>(b2, h2);

    // GEMM3 + gumbel softmax
    final_k<<<B_, 128>>>(h2, W3, b3, gn, out);
}